// round 14
// baseline (speedup 1.0000x reference)
#include <cuda_runtime.h>
#include <cuda_fp16.h>
#include <cstdint>

// ---------------------------------------------------------------------------
// out = mean_s( B2_s B1_s patch_s + bias_s )  ==  3x3 conv 256->256, pad 1.
// Collapsed GEMM D[m,n] = sum_k A[m,k]*B[n,k], m=16384, n=256, k=2304.
// R14: latency attack on the HMMA mainloop — hoisted SW128 addressing
// (single-XOR identity), A-fragment register double buffering. Math order
// unchanged (bitwise-identical result vs R13).
// ---------------------------------------------------------------------------

#define B_   16
#define C_   256
#define N_   256
#define HW_  1024
#define KTOT 2304
#define PAD_ 34
#define NCH  36

// ------------------------- device scratch (no alloc) -----------------------
__device__ __align__(16) __half g_Bh[N_ * KTOT];              // W [n][tap*256+c] * 1/144
__device__ __align__(16) __half g_Ah[B_ * PAD_ * PAD_ * C_];  // x [b][py][px][c] fp16

// ------------------------------ PTX helpers --------------------------------
__device__ __forceinline__ uint32_t smem_u32(const void* p) {
    uint32_t a;
    asm("{ .reg .u64 t; cvta.to.shared.u64 t, %1; cvt.u32.u64 %0, t; }"
        : "=r"(a) : "l"(p));
    return a;
}
#define SW128(o) ((o) ^ ((((uint32_t)(o)) >> 3) & 0x70))

#define CP_ASYNC16(dst, src) \
    asm volatile("cp.async.cg.shared.global [%0], [%1], 16;" \
                 :: "r"(dst), "l"(src) : "memory")
#define CP_COMMIT() asm volatile("cp.async.commit_group;" ::: "memory")
#define CP_WAIT(n)  asm volatile("cp.async.wait_group %0;" :: "n"(n) : "memory")

__device__ __forceinline__ void ldmx4(uint32_t* r, uint32_t addr) {
    asm volatile("ldmatrix.sync.aligned.m8n8.x4.shared.b16 {%0,%1,%2,%3}, [%4];"
                 : "=r"(r[0]), "=r"(r[1]), "=r"(r[2]), "=r"(r[3]) : "r"(addr));
}
__device__ __forceinline__ void mma16816(float* d, const uint32_t* a,
                                         uint32_t b0, uint32_t b1) {
    asm volatile(
        "mma.sync.aligned.m16n8k16.row.col.f32.f16.f16.f32 "
        "{%0,%1,%2,%3}, {%4,%5,%6,%7}, {%8,%9}, {%0,%1,%2,%3};"
        : "+f"(d[0]), "+f"(d[1]), "+f"(d[2]), "+f"(d[3])
        : "r"(a[0]), "r"(a[1]), "r"(a[2]), "r"(a[3]), "r"(b0), "r"(b1));
}

// ---------------------------------------------------------------------------
// Kernel 1 (merged prep): blocks 0..143 build butterfly weight matrices,
// blocks 144..655 transpose+convert the input (concurrent execution).
// ---------------------------------------------------------------------------
#define BFLY_BLKS 144
#define PREP_BLKS (BFLY_BLKS + 512)

__global__ void __launch_bounds__(256)
prep_kernel(const float* __restrict__ tw1, const float* __restrict__ tw2,
            const float* __restrict__ x) {
    __shared__ float sm[256 * 33];
    const int bid = blockIdx.x;
    const int tid = threadIdx.x;

    if (bid < BFLY_BLKS) {
        // ---- butterfly build: M_s = B2_s * B1_s -> fp16 * 1/144 ----
        float* M = sm;                       // pitch 17
        const int s     = bid / 16;
        const int chunk = bid & 15;

        for (int idx = tid; idx < 256 * 16; idx += 256) {
            int n = idx >> 4, col = idx & 15;
            M[n * 17 + col] = (n == chunk * 16 + col) ? 1.0f : 0.0f;
        }

        auto stage = [&](const float* __restrict__ tw, int sh) {
            __syncthreads();
            const int st = 1 << sh;
            for (int task = tid; task < 128 * 16; task += 256) {
                int pr  = task >> 4, col = task & 15;
                int l   = pr & (st - 1);
                int k0  = ((pr >> sh) << (sh + 1)) | l;
                int k1  = k0 + st;
                const float4 t = *(const float4*)(tw + ((size_t)s * 255 + (st - 1) + l) * 4);
                float a = M[k0 * 17 + col];
                float b = M[k1 * 17 + col];
                M[k0 * 17 + col] = t.x * a + t.y * b;
                M[k1 * 17 + col] = t.z * a + t.w * b;
            }
        };

        for (int sh = 7; sh >= 0; --sh) stage(tw1, sh);   // increasing=False
        for (int sh = 0; sh <= 7; ++sh) stage(tw2, sh);   // increasing=True

        __syncthreads();
        const float sc = 1.0f / (9.0f * 16.0f);
        for (int idx = tid; idx < 256 * 16; idx += 256) {
            int col = idx & 15, n = idx >> 4;
            int c = chunk * 16 + col;
            g_Bh[(size_t)n * KTOT + s * 256 + c] = __float2half(M[n * 17 + col] * sc);
        }
    } else {
        // ---- input transpose + fp16 + border zero ----
        const int sbid = bid - BFLY_BLKS;
        const int b = sbid >> 5;
        const int y = sbid & 31;

        {
            int idx = sbid * 256 + tid;
            if (idx < 16 * 132 * 32) {
                int vec  = idx & 31;
                int cell = (idx >> 5) % 132;
                int bb   = idx / (132 * 32);
                int py, px;
                if (cell < 34)      { py = 0;  px = cell; }
                else if (cell < 68) { py = 33; px = cell - 34; }
                else { int r = cell - 68; py = 1 + (r >> 1); px = (r & 1) * 33; }
                size_t base = (((size_t)bb * PAD_ + py) * PAD_ + px) * 256;
                ((uint4*)(g_Ah + base))[vec] = make_uint4(0, 0, 0, 0);
            }
        }

        const int w = tid >> 5, xc = tid & 31;
        #pragma unroll 4
        for (int i = 0; i < 32; ++i) {
            int c = i * 8 + w;
            sm[c * 33 + xc] = x[(((size_t)b * 256 + c) * 32 + y) * 32 + xc];
        }
        __syncthreads();

        #pragma unroll 4
        for (int xi = 0; xi < 32; ++xi) {
            float v = sm[tid * 33 + xi];
            g_Ah[(((size_t)b * PAD_ + y + 1) * PAD_ + xi + 1) * 256 + tid] = __float2half(v);
        }
    }
}

// ---------------------------------------------------------------------------
// Kernel 2: fp16 HMMA GEMM. CTA tile 128M x 128N, 8 warps (4M x 2N), warp
// 32x64 via m16n8k16. 36 K-chunks of 64, 3-stage cp.async ring.
// Hoisted swizzled addressing + A-frag register double buffer.
// ---------------------------------------------------------------------------
#define A_ST 16384
#define B_OF 49152
#define SMEM_TOT 98304

__global__ void __launch_bounds__(256, 2)
gemm_kernel(const float* __restrict__ bias, float* __restrict__ out) {
    extern __shared__ char smem[];
    const uint32_t sb = smem_u32(smem);
    const int tid  = threadIdx.x;
    const int lane = tid & 31;
    const int wid  = tid >> 5;
    const int wm   = wid & 3;
    const int wn   = wid >> 2;

    const int blk = blockIdx.x;
    const int b   = blk >> 3;
    const int y0  = (blk & 7) * 4;
    const int n0  = blockIdx.y * 128;

    float acc[2][8][4];
    #pragma unroll
    for (int mi = 0; mi < 2; ++mi)
        #pragma unroll
        for (int ni = 0; ni < 8; ++ni)
            #pragma unroll
            for (int v = 0; v < 4; ++v) acc[mi][ni][v] = 0.f;

    // ---- hoisted cp.async addressing ----
    const int arow  = tid >> 1;            // 0..127
    const int ahalf = tid & 1;
    // swizzled dest offsets: row*128 + ((ahalf*64 + q*16) ^ ((arow&7)<<4))
    uint32_t dq[4];
    {
        const uint32_t xr = (uint32_t)(arow & 7) << 4;
        #pragma unroll
        for (int q = 0; q < 4; ++q)
            dq[q] = (uint32_t)arow * 128 + (((uint32_t)ahalf * 64 + q * 16) ^ xr);
    }
    // per-thread global base pointers (tap 0, cc 0)
    const char* aptr = (const char*)(g_Ah +
        (((size_t)b * PAD_ + y0 + (arow >> 5)) * PAD_ + (arow & 31)) * 256) + ahalf * 64;
    const char* bptr = (const char*)(g_Bh + (size_t)(n0 + arow) * KTOT) + ahalf * 64;

    // ---- hoisted ldmatrix addressing ----
    const uint32_t lrow = lane & 15;
    const uint32_t lcol = (lane >> 4) * 16;
    const uint32_t xorv = (lrow & 7) << 4;
    uint32_t cv[4];
    #pragma unroll
    for (int ks = 0; ks < 4; ++ks) cv[ks] = (ks * 32 + lcol) ^ xorv;
    const uint32_t a0 = (wm * 32 + lrow) * 128;           // + mi*2048
    const uint32_t b0 = (wn * 64 + lrow) * 128;           // + nq*2048

    // cp.async issue for chunk ch into stage j
    auto load_chunk = [&](int j, int ch) {
        const int tap = ch >> 2;
        const int cc  = ch & 3;
        const int dy  = tap / 3, dx = tap - dy * 3;
        const int aoff = ((dy * PAD_ + dx) * 256 + cc * 64) * 2;  // bytes
        const int boff = (tap * 256 + cc * 64) * 2;               // bytes
        const uint32_t ac = sb + (uint32_t)j * A_ST;
        const uint32_t bc = ac + B_OF;
        const char* as = aptr + aoff;
        const char* bs = bptr + boff;
        #pragma unroll
        for (int q = 0; q < 4; ++q) CP_ASYNC16(ac + dq[q], as + q * 16);
        #pragma unroll
        for (int q = 0; q < 4; ++q) CP_ASYNC16(bc + dq[q], bs + q * 16);
    };

    load_chunk(0, 0);
    CP_COMMIT();
    load_chunk(1, 1);
    CP_COMMIT();

    int stg = 0;
    for (int i = 0; i < NCH; ++i) {
        if (i + 1 < NCH) { CP_WAIT(1); } else { CP_WAIT(0); }
        __syncthreads();
        if (i + 2 < NCH) {
            load_chunk((i + 2) % 3, i + 2);
            CP_COMMIT();
        }

        const uint32_t ab = sb + (uint32_t)stg * A_ST;
        const uint32_t bb = ab + B_OF;

        // A-frag double buffer: prefetch ks=0
        uint32_t afr[2][2][4];
        ldmx4(afr[0][0], ab + a0 + cv[0]);
        ldmx4(afr[0][1], ab + a0 + 2048 + cv[0]);

        #pragma unroll
        for (int ks = 0; ks < 4; ++ks) {
            const int cur = ks & 1;
            uint32_t bfr[4][4];
            #pragma unroll
            for (int nq = 0; nq < 4; ++nq)
                ldmx4(bfr[nq], bb + b0 + nq * 2048 + cv[ks]);
            if (ks < 3) {
                ldmx4(afr[cur ^ 1][0], ab + a0 + cv[ks + 1]);
                ldmx4(afr[cur ^ 1][1], ab + a0 + 2048 + cv[ks + 1]);
            }
            #pragma unroll
            for (int mi = 0; mi < 2; ++mi)
                #pragma unroll
                for (int ni = 0; ni < 8; ++ni)
                    mma16816(acc[mi][ni], afr[cur][mi],
                             bfr[ni >> 1][ni & 1], bfr[ni >> 1][(ni & 1) + 2]);
        }
        stg = (stg + 1) % 3;
    }

    // epilogue: mean bias per col, acc*16 (undo B scaling), store
    float bias2[8][2];
    #pragma unroll
    for (int ni = 0; ni < 8; ++ni) {
        const int n = n0 + wn * 64 + ni * 8 + (lane & 3) * 2;
        float s0 = 0.f, s1 = 0.f;
        #pragma unroll
        for (int s = 0; s < 9; ++s) {
            s0 += bias[s * 256 + n];
            s1 += bias[s * 256 + n + 1];
        }
        bias2[ni][0] = s0 * (1.0f / 9.0f);
        bias2[ni][1] = s1 * (1.0f / 9.0f);
    }
    #pragma unroll
    for (int mi = 0; mi < 2; ++mi) {
        const int rbase = wm * 32 + mi * 16 + (lane >> 2);
        #pragma unroll
        for (int ni = 0; ni < 8; ++ni) {
            const int n = n0 + wn * 64 + ni * 8 + (lane & 3) * 2;
            #pragma unroll
            for (int hrow = 0; hrow < 2; ++hrow) {
                const int row = rbase + hrow * 8;
                const int yy = row >> 5, xx = row & 31;
                float* op = out + (((size_t)b * N_ + n) * 32 + y0 + yy) * 32 + xx;
                op[0]   = acc[mi][ni][2 * hrow]     * 16.0f + bias2[ni][0];
                op[HW_] = acc[mi][ni][2 * hrow + 1] * 16.0f + bias2[ni][1];
            }
        }
    }
}

// ---------------------------------------------------------------------------
extern "C" void kernel_launch(void* const* d_in, const int* in_sizes, int n_in,
                              void* d_out, int out_size) {
    const float* x    = (const float*)d_in[0];
    const float* tw1  = (const float*)d_in[1];
    const float* tw2  = (const float*)d_in[2];
    const float* bias = (const float*)d_in[3];
    float* out = (float*)d_out;

    cudaFuncSetAttribute(gemm_kernel,
                         cudaFuncAttributeMaxDynamicSharedMemorySize, SMEM_TOT);

    prep_kernel<<<PREP_BLKS, 256>>>(tw1, tw2, x);
    gemm_kernel<<<dim3(128, 2), 256, SMEM_TOT>>>(bias, out);
}

// round 15
// speedup vs baseline: 1.4507x; 1.4507x over previous
#include <cuda_runtime.h>
#include <cuda_fp16.h>
#include <cstdint>

// ---------------------------------------------------------------------------
// out = mean_s( B2_s B1_s patch_s + bias_s )  ==  3x3 conv 256->256, pad 1.
// Collapsed GEMM D[m,n] = sum_k A[m,k]*B[n,k], m=16384, n=256, k=2304.
// R15: occupancy attack. CTA tile 64Mx128N (8 warps of 32x32), 3-stage ring
// 72KB smem -> 3 CTAs/SM (6 warps/SMSP), launch_bounds(256,3) (85-reg cap,
// acc only 32 regs). Mainloop body identical in structure to R13 (known
// good); per-element accumulation order unchanged -> rel_err bit-identical.
// ---------------------------------------------------------------------------

#define B_   16
#define C_   256
#define N_   256
#define HW_  1024
#define KTOT 2304
#define PAD_ 34
#define NCH  36

// ------------------------- device scratch (no alloc) -----------------------
__device__ __align__(16) __half g_Bh[N_ * KTOT];              // W [n][tap*256+c] * 1/144
__device__ __align__(16) __half g_Ah[B_ * PAD_ * PAD_ * C_];  // x [b][py][px][c] fp16

// ------------------------------ PTX helpers --------------------------------
__device__ __forceinline__ uint32_t smem_u32(const void* p) {
    uint32_t a;
    asm("{ .reg .u64 t; cvta.to.shared.u64 t, %1; cvt.u32.u64 %0, t; }"
        : "=r"(a) : "l"(p));
    return a;
}
#define SW128(o) ((o) ^ ((((uint32_t)(o)) >> 3) & 0x70))

#define CP_ASYNC16(dst, src) \
    asm volatile("cp.async.cg.shared.global [%0], [%1], 16;" \
                 :: "r"(dst), "l"(src) : "memory")
#define CP_COMMIT() asm volatile("cp.async.commit_group;" ::: "memory")
#define CP_WAIT(n)  asm volatile("cp.async.wait_group %0;" :: "n"(n) : "memory")

__device__ __forceinline__ void ldmx4(uint32_t* r, uint32_t addr) {
    asm volatile("ldmatrix.sync.aligned.m8n8.x4.shared.b16 {%0,%1,%2,%3}, [%4];"
                 : "=r"(r[0]), "=r"(r[1]), "=r"(r[2]), "=r"(r[3]) : "r"(addr));
}
__device__ __forceinline__ void mma16816(float* d, const uint32_t* a,
                                         uint32_t b0, uint32_t b1) {
    asm volatile(
        "mma.sync.aligned.m16n8k16.row.col.f32.f16.f16.f32 "
        "{%0,%1,%2,%3}, {%4,%5,%6,%7}, {%8,%9}, {%0,%1,%2,%3};"
        : "+f"(d[0]), "+f"(d[1]), "+f"(d[2]), "+f"(d[3])
        : "r"(a[0]), "r"(a[1]), "r"(a[2]), "r"(a[3]), "r"(b0), "r"(b1));
}

// ---------------------------------------------------------------------------
// Kernel 1 (merged prep): blocks 0..143 build butterfly weight matrices,
// blocks 144..655 transpose+convert the input (concurrent execution).
// ---------------------------------------------------------------------------
#define BFLY_BLKS 144
#define PREP_BLKS (BFLY_BLKS + 512)

__global__ void __launch_bounds__(256)
prep_kernel(const float* __restrict__ tw1, const float* __restrict__ tw2,
            const float* __restrict__ x) {
    __shared__ float sm[256 * 33];
    const int bid = blockIdx.x;
    const int tid = threadIdx.x;

    if (bid < BFLY_BLKS) {
        // ---- butterfly build: M_s = B2_s * B1_s -> fp16 * 1/144 ----
        float* M = sm;                       // pitch 17
        const int s     = bid / 16;
        const int chunk = bid & 15;

        for (int idx = tid; idx < 256 * 16; idx += 256) {
            int n = idx >> 4, col = idx & 15;
            M[n * 17 + col] = (n == chunk * 16 + col) ? 1.0f : 0.0f;
        }

        auto stage = [&](const float* __restrict__ tw, int sh) {
            __syncthreads();
            const int st = 1 << sh;
            for (int task = tid; task < 128 * 16; task += 256) {
                int pr  = task >> 4, col = task & 15;
                int l   = pr & (st - 1);
                int k0  = ((pr >> sh) << (sh + 1)) | l;
                int k1  = k0 + st;
                const float4 t = *(const float4*)(tw + ((size_t)s * 255 + (st - 1) + l) * 4);
                float a = M[k0 * 17 + col];
                float b = M[k1 * 17 + col];
                M[k0 * 17 + col] = t.x * a + t.y * b;
                M[k1 * 17 + col] = t.z * a + t.w * b;
            }
        };

        for (int sh = 7; sh >= 0; --sh) stage(tw1, sh);   // increasing=False
        for (int sh = 0; sh <= 7; ++sh) stage(tw2, sh);   // increasing=True

        __syncthreads();
        const float sc = 1.0f / (9.0f * 16.0f);
        for (int idx = tid; idx < 256 * 16; idx += 256) {
            int col = idx & 15, n = idx >> 4;
            int c = chunk * 16 + col;
            g_Bh[(size_t)n * KTOT + s * 256 + c] = __float2half(M[n * 17 + col] * sc);
        }
    } else {
        // ---- input transpose + fp16 + border zero ----
        const int sbid = bid - BFLY_BLKS;
        const int b = sbid >> 5;
        const int y = sbid & 31;

        {
            int idx = sbid * 256 + tid;
            if (idx < 16 * 132 * 32) {
                int vec  = idx & 31;
                int cell = (idx >> 5) % 132;
                int bb   = idx / (132 * 32);
                int py, px;
                if (cell < 34)      { py = 0;  px = cell; }
                else if (cell < 68) { py = 33; px = cell - 34; }
                else { int r = cell - 68; py = 1 + (r >> 1); px = (r & 1) * 33; }
                size_t base = (((size_t)bb * PAD_ + py) * PAD_ + px) * 256;
                ((uint4*)(g_Ah + base))[vec] = make_uint4(0, 0, 0, 0);
            }
        }

        const int w = tid >> 5, xc = tid & 31;
        #pragma unroll 4
        for (int i = 0; i < 32; ++i) {
            int c = i * 8 + w;
            sm[c * 33 + xc] = x[(((size_t)b * 256 + c) * 32 + y) * 32 + xc];
        }
        __syncthreads();

        #pragma unroll 4
        for (int xi = 0; xi < 32; ++xi) {
            float v = sm[tid * 33 + xi];
            g_Ah[(((size_t)b * PAD_ + y + 1) * PAD_ + xi + 1) * 256 + tid] = __float2half(v);
        }
    }
}

// ---------------------------------------------------------------------------
// Kernel 2: fp16 HMMA GEMM. CTA tile 64M x 128N, 8 warps (2M x 4N), warp
// 32x32 via m16n8k16. 36 K-chunks of 64, 3-stage cp.async ring (single
// barrier per iteration). Stage = 8KB A + 16KB B. Epilogue: acc*16 + bias.
// ---------------------------------------------------------------------------
#define STG_SZ 24576
#define B_OF   8192
#define SMEM_TOT (3 * STG_SZ)        // 73728

__device__ __forceinline__ void load_chunk(uint32_t sb, int j, int ch,
                                           int b, int y0, int n0, int tid) {
    const int tap = ch >> 2;
    const int cc  = ch & 3;
    const int dy  = tap / 3, dx = tap - dy * 3;
    const int cbase = cc * 64;

    const uint32_t stbase = sb + (uint32_t)j * STG_SZ;

    // A tile: 64 rows x 128B. thread -> row tid>>2, quarter (32B) tid&3.
    {
        const int arow = tid >> 2, aq = tid & 3;
        const int py = y0 + (arow >> 5) + dy;
        const int px = (arow & 31) + dx;
        const char* asrc = (const char*)(g_Ah +
            (((size_t)b * PAD_ + py) * PAD_ + px) * 256 + cbase) + aq * 32;
        const uint32_t ro = (uint32_t)arow * 128 + aq * 32;
        #pragma unroll
        for (int q = 0; q < 2; ++q)
            CP_ASYNC16(stbase + SW128(ro + q * 16), asrc + q * 16);
    }
    // B tile: 128 rows x 128B. thread -> row tid>>1, half (64B) tid&1.
    {
        const int brow = tid >> 1, bhalf = tid & 1;
        const char* bsrc = (const char*)(g_Bh +
            (size_t)(n0 + brow) * KTOT + tap * 256 + cbase) + bhalf * 64;
        const uint32_t ro = (uint32_t)brow * 128 + bhalf * 64;
        #pragma unroll
        for (int q = 0; q < 4; ++q)
            CP_ASYNC16(stbase + B_OF + SW128(ro + q * 16), bsrc + q * 16);
    }
}

__global__ void __launch_bounds__(256, 3)
gemm_kernel(const float* __restrict__ bias, float* __restrict__ out) {
    extern __shared__ char smem[];
    const uint32_t sb = smem_u32(smem);
    const int tid  = threadIdx.x;
    const int lane = tid & 31;
    const int wid  = tid >> 5;
    const int wm   = wid & 1;              // 2 M-warps (32 rows each)
    const int wn   = wid >> 1;             // 4 N-warps (32 cols each)

    const int blk = blockIdx.x;            // 256 M-tiles of 64 rows
    const int b   = blk >> 4;
    const int y0  = (blk & 15) * 2;        // 2 image rows per tile
    const int n0  = blockIdx.y * 128;

    float acc[2][4][4];
    #pragma unroll
    for (int mi = 0; mi < 2; ++mi)
        #pragma unroll
        for (int ni = 0; ni < 4; ++ni)
            #pragma unroll
            for (int v = 0; v < 4; ++v) acc[mi][ni][v] = 0.f;

    const uint32_t lrow = lane & 15;
    const uint32_t lcol = (lane >> 4) * 16;

    load_chunk(sb, 0, 0, b, y0, n0, tid);
    CP_COMMIT();
    load_chunk(sb, 1, 1, b, y0, n0, tid);
    CP_COMMIT();

    int stg = 0;
    for (int i = 0; i < NCH; ++i) {
        if (i + 1 < NCH) { CP_WAIT(1); } else { CP_WAIT(0); }
        __syncthreads();
        if (i + 2 < NCH) {
            load_chunk(sb, (i + 2) % 3, i + 2, b, y0, n0, tid);
            CP_COMMIT();
        }

        const uint32_t ab = sb + (uint32_t)stg * STG_SZ;
        const uint32_t bb = ab + B_OF;

        #pragma unroll
        for (int ks = 0; ks < 4; ++ks) {
            uint32_t afr[2][4];
            #pragma unroll
            for (int mi = 0; mi < 2; ++mi) {
                uint32_t row = wm * 32 + mi * 16 + lrow;
                ldmx4(afr[mi], ab + SW128(row * 128 + ks * 32 + lcol));
            }
            uint32_t bfr[2][4];
            #pragma unroll
            for (int nq = 0; nq < 2; ++nq) {
                uint32_t row = wn * 32 + nq * 16 + lrow;
                ldmx4(bfr[nq], bb + SW128(row * 128 + ks * 32 + lcol));
            }
            #pragma unroll
            for (int mi = 0; mi < 2; ++mi)
                #pragma unroll
                for (int ni = 0; ni < 4; ++ni)
                    mma16816(acc[mi][ni], afr[mi],
                             bfr[ni >> 1][ni & 1], bfr[ni >> 1][(ni & 1) + 2]);
        }
        stg = (stg + 1) % 3;
    }

    // epilogue: mean bias per col, acc*16 (undo B scaling), store
    float bias2[4][2];
    #pragma unroll
    for (int ni = 0; ni < 4; ++ni) {
        const int n = n0 + wn * 32 + ni * 8 + (lane & 3) * 2;
        float s0 = 0.f, s1 = 0.f;
        #pragma unroll
        for (int s = 0; s < 9; ++s) {
            s0 += bias[s * 256 + n];
            s1 += bias[s * 256 + n + 1];
        }
        bias2[ni][0] = s0 * (1.0f / 9.0f);
        bias2[ni][1] = s1 * (1.0f / 9.0f);
    }
    #pragma unroll
    for (int mi = 0; mi < 2; ++mi) {
        const int rbase = wm * 32 + mi * 16 + (lane >> 2);
        #pragma unroll
        for (int ni = 0; ni < 4; ++ni) {
            const int n = n0 + wn * 32 + ni * 8 + (lane & 3) * 2;
            #pragma unroll
            for (int hrow = 0; hrow < 2; ++hrow) {
                const int row = rbase + hrow * 8;
                const int yy = row >> 5, xx = row & 31;
                float* op = out + (((size_t)b * N_ + n) * 32 + y0 + yy) * 32 + xx;
                op[0]   = acc[mi][ni][2 * hrow]     * 16.0f + bias2[ni][0];
                op[HW_] = acc[mi][ni][2 * hrow + 1] * 16.0f + bias2[ni][1];
            }
        }
    }
}

// ---------------------------------------------------------------------------
extern "C" void kernel_launch(void* const* d_in, const int* in_sizes, int n_in,
                              void* d_out, int out_size) {
    const float* x    = (const float*)d_in[0];
    const float* tw1  = (const float*)d_in[1];
    const float* tw2  = (const float*)d_in[2];
    const float* bias = (const float*)d_in[3];
    float* out = (float*)d_out;

    cudaFuncSetAttribute(gemm_kernel,
                         cudaFuncAttributeMaxDynamicSharedMemorySize, SMEM_TOT);

    prep_kernel<<<PREP_BLKS, 256>>>(tw1, tw2, x);
    gemm_kernel<<<dim3(256, 2), 256, SMEM_TOT>>>(bias, out);
}

// round 17
// speedup vs baseline: 1.6524x; 1.1390x over previous
#include <cuda_runtime.h>
#include <cuda_fp16.h>
#include <cstdint>

// ---------------------------------------------------------------------------
// out = mean_s( B2_s B1_s patch_s + bias_s )  ==  3x3 conv 256->256, pad 1.
// Collapsed GEMM D[m,n] = sum_k A[m,k]*B[n,k], m=16384, n=256, k=2304.
// R16: 1 CTA/SM. Tile 128M x 256N (full N), 512 threads, 16 warps (4x4),
// warp 32x64 (same math order as R13 -> rel_err bit-identical). 255-reg
// budget enables A+B fragment double-buffering (the R14 idea without the
// spill). 36 K-chunks of 64, 3-stage cp.async ring, 48KB/stage.
// ---------------------------------------------------------------------------

#define B_   16
#define C_   256
#define N_   256
#define HW_  1024
#define KTOT 2304
#define PAD_ 34
#define NCH  36

// ------------------------- device scratch (no alloc) -----------------------
__device__ __align__(16) __half g_Bh[N_ * KTOT];              // W [n][tap*256+c] * 1/144
__device__ __align__(16) __half g_Ah[B_ * PAD_ * PAD_ * C_];  // x [b][py][px][c] fp16

// ------------------------------ PTX helpers --------------------------------
__device__ __forceinline__ uint32_t smem_u32(const void* p) {
    uint32_t a;
    asm("{ .reg .u64 t; cvta.to.shared.u64 t, %1; cvt.u32.u64 %0, t; }"
        : "=r"(a) : "l"(p));
    return a;
}
#define SW128(o) ((o) ^ ((((uint32_t)(o)) >> 3) & 0x70))

#define CP_ASYNC16(dst, src) \
    asm volatile("cp.async.cg.shared.global [%0], [%1], 16;" \
                 :: "r"(dst), "l"(src) : "memory")
#define CP_COMMIT() asm volatile("cp.async.commit_group;" ::: "memory")
#define CP_WAIT(n)  asm volatile("cp.async.wait_group %0;" :: "n"(n) : "memory")

__device__ __forceinline__ void ldmx4(uint32_t* r, uint32_t addr) {
    asm volatile("ldmatrix.sync.aligned.m8n8.x4.shared.b16 {%0,%1,%2,%3}, [%4];"
                 : "=r"(r[0]), "=r"(r[1]), "=r"(r[2]), "=r"(r[3]) : "r"(addr));
}
__device__ __forceinline__ void mma16816(float* d, const uint32_t* a,
                                         uint32_t b0, uint32_t b1) {
    asm volatile(
        "mma.sync.aligned.m16n8k16.row.col.f32.f16.f16.f32 "
        "{%0,%1,%2,%3}, {%4,%5,%6,%7}, {%8,%9}, {%0,%1,%2,%3};"
        : "+f"(d[0]), "+f"(d[1]), "+f"(d[2]), "+f"(d[3])
        : "r"(a[0]), "r"(a[1]), "r"(a[2]), "r"(a[3]), "r"(b0), "r"(b1));
}

// ---------------------------------------------------------------------------
// Kernel 1 (merged prep): blocks 0..143 build butterfly weight matrices,
// blocks 144..655 transpose+convert the input (concurrent execution).
// ---------------------------------------------------------------------------
#define BFLY_BLKS 144
#define PREP_BLKS (BFLY_BLKS + 512)

__global__ void __launch_bounds__(256)
prep_kernel(const float* __restrict__ tw1, const float* __restrict__ tw2,
            const float* __restrict__ x) {
    __shared__ float sm[256 * 33];
    const int bid = blockIdx.x;
    const int tid = threadIdx.x;

    if (bid < BFLY_BLKS) {
        // ---- butterfly build: M_s = B2_s * B1_s -> fp16 * 1/144 ----
        float* M = sm;                       // pitch 17
        const int s     = bid / 16;
        const int chunk = bid & 15;

        for (int idx = tid; idx < 256 * 16; idx += 256) {
            int n = idx >> 4, col = idx & 15;
            M[n * 17 + col] = (n == chunk * 16 + col) ? 1.0f : 0.0f;
        }

        auto stage = [&](const float* __restrict__ tw, int sh) {
            __syncthreads();
            const int st = 1 << sh;
            for (int task = tid; task < 128 * 16; task += 256) {
                int pr  = task >> 4, col = task & 15;
                int l   = pr & (st - 1);
                int k0  = ((pr >> sh) << (sh + 1)) | l;
                int k1  = k0 + st;
                const float4 t = *(const float4*)(tw + ((size_t)s * 255 + (st - 1) + l) * 4);
                float a = M[k0 * 17 + col];
                float b = M[k1 * 17 + col];
                M[k0 * 17 + col] = t.x * a + t.y * b;
                M[k1 * 17 + col] = t.z * a + t.w * b;
            }
        };

        for (int sh = 7; sh >= 0; --sh) stage(tw1, sh);   // increasing=False
        for (int sh = 0; sh <= 7; ++sh) stage(tw2, sh);   // increasing=True

        __syncthreads();
        const float sc = 1.0f / (9.0f * 16.0f);
        for (int idx = tid; idx < 256 * 16; idx += 256) {
            int col = idx & 15, n = idx >> 4;
            int c = chunk * 16 + col;
            g_Bh[(size_t)n * KTOT + s * 256 + c] = __float2half(M[n * 17 + col] * sc);
        }
    } else {
        // ---- input transpose + fp16 + border zero ----
        const int sbid = bid - BFLY_BLKS;
        const int b = sbid >> 5;
        const int y = sbid & 31;

        {
            int idx = sbid * 256 + tid;
            if (idx < 16 * 132 * 32) {
                int vec  = idx & 31;
                int cell = (idx >> 5) % 132;
                int bb   = idx / (132 * 32);
                int py, px;
                if (cell < 34)      { py = 0;  px = cell; }
                else if (cell < 68) { py = 33; px = cell - 34; }
                else { int r = cell - 68; py = 1 + (r >> 1); px = (r & 1) * 33; }
                size_t base = (((size_t)bb * PAD_ + py) * PAD_ + px) * 256;
                ((uint4*)(g_Ah + base))[vec] = make_uint4(0, 0, 0, 0);
            }
        }

        const int w = tid >> 5, xc = tid & 31;
        #pragma unroll 4
        for (int i = 0; i < 32; ++i) {
            int c = i * 8 + w;
            sm[c * 33 + xc] = x[(((size_t)b * 256 + c) * 32 + y) * 32 + xc];
        }
        __syncthreads();

        #pragma unroll 4
        for (int xi = 0; xi < 32; ++xi) {
            float v = sm[tid * 33 + xi];
            g_Ah[(((size_t)b * PAD_ + y + 1) * PAD_ + xi + 1) * 256 + tid] = __float2half(v);
        }
    }
}

// ---------------------------------------------------------------------------
// Kernel 2: fp16 HMMA GEMM. 1 CTA/SM: tile 128M x 256N, 512 threads,
// 16 warps (4 wm x 4 wn), warp 32x64 via m16n8k16. 36 K-chunks of 64,
// 3-stage cp.async ring (A 16KB + B 32KB per stage), fragment double
// buffering across ks. Epilogue: acc*16 + mean(bias).
// ---------------------------------------------------------------------------
#define STG_SZ 49152
#define B_OF   16384
#define SMEM_TOT (3 * STG_SZ)        // 147456

__device__ __forceinline__ void load_chunk(uint32_t sb, int j, int ch,
                                           int b, int y0, int tid) {
    const int tap = ch >> 2;
    const int cc  = ch & 3;
    const int dy  = tap / 3, dx = tap - dy * 3;
    const int cbase = cc * 64;

    const uint32_t stbase = sb + (uint32_t)j * STG_SZ;

    // A tile: 128 rows x 128B; thread -> row tid>>2, quarter (32B) tid&3.
    {
        const int arow = tid >> 2, aq = tid & 3;
        const int py = y0 + (arow >> 5) + dy;
        const int px = (arow & 31) + dx;
        const char* asrc = (const char*)(g_Ah +
            (((size_t)b * PAD_ + py) * PAD_ + px) * 256 + cbase) + aq * 32;
        const uint32_t ro = (uint32_t)arow * 128 + aq * 32;
        #pragma unroll
        for (int q = 0; q < 2; ++q)
            CP_ASYNC16(stbase + SW128(ro + q * 16), asrc + q * 16);
    }
    // B tile: 256 rows x 128B; thread -> row tid>>1, half (64B) tid&1.
    {
        const int brow = tid >> 1, bhalf = tid & 1;
        const char* bsrc = (const char*)(g_Bh +
            (size_t)brow * KTOT + tap * 256 + cbase) + bhalf * 64;
        const uint32_t ro = (uint32_t)brow * 128 + bhalf * 64;
        #pragma unroll
        for (int q = 0; q < 4; ++q)
            CP_ASYNC16(stbase + B_OF + SW128(ro + q * 16), bsrc + q * 16);
    }
}

__global__ void __launch_bounds__(512, 1)
gemm_kernel(const float* __restrict__ bias, float* __restrict__ out) {
    extern __shared__ char smem[];
    const uint32_t sb = smem_u32(smem);
    const int tid  = threadIdx.x;
    const int lane = tid & 31;
    const int wid  = tid >> 5;             // 0..15
    const int wm   = wid & 3;              // 4 M-groups of 32 rows
    const int wn   = wid >> 2;             // 4 N-groups of 64 cols

    const int blk = blockIdx.x;            // 128 M-tiles
    const int b   = blk >> 3;
    const int y0  = (blk & 7) * 4;

    float acc[2][8][4];
    #pragma unroll
    for (int mi = 0; mi < 2; ++mi)
        #pragma unroll
        for (int ni = 0; ni < 8; ++ni)
            #pragma unroll
            for (int v = 0; v < 4; ++v) acc[mi][ni][v] = 0.f;

    const uint32_t lrow = lane & 15;
    const uint32_t lcol = (lane >> 4) * 16;

    load_chunk(sb, 0, 0, b, y0, tid);
    CP_COMMIT();
    load_chunk(sb, 1, 1, b, y0, tid);
    CP_COMMIT();

    int stg = 0;
    for (int i = 0; i < NCH; ++i) {
        if (i + 1 < NCH) { CP_WAIT(1); } else { CP_WAIT(0); }
        __syncthreads();
        if (i + 2 < NCH) {
            load_chunk(sb, (i + 2) % 3, i + 2, b, y0, tid);
            CP_COMMIT();
        }

        const uint32_t ab = sb + (uint32_t)stg * STG_SZ;
        const uint32_t bb = ab + B_OF;

        // fragment double buffer across ks (reg budget: occ 1, 255 regs)
        uint32_t afr[2][2][4], bfr[2][4][4];
        #pragma unroll
        for (int mi = 0; mi < 2; ++mi)
            ldmx4(afr[0][mi], ab + SW128((wm * 32 + mi * 16 + lrow) * 128 + lcol));
        #pragma unroll
        for (int nq = 0; nq < 4; ++nq)
            ldmx4(bfr[0][nq], bb + SW128((wn * 64 + nq * 16 + lrow) * 128 + lcol));

        #pragma unroll
        for (int ks = 0; ks < 4; ++ks) {
            const int cur = ks & 1;
            if (ks < 3) {
                #pragma unroll
                for (int mi = 0; mi < 2; ++mi)
                    ldmx4(afr[cur ^ 1][mi],
                          ab + SW128((wm * 32 + mi * 16 + lrow) * 128 + (ks + 1) * 32 + lcol));
                #pragma unroll
                for (int nq = 0; nq < 4; ++nq)
                    ldmx4(bfr[cur ^ 1][nq],
                          bb + SW128((wn * 64 + nq * 16 + lrow) * 128 + (ks + 1) * 32 + lcol));
            }
            #pragma unroll
            for (int mi = 0; mi < 2; ++mi)
                #pragma unroll
                for (int ni = 0; ni < 8; ++ni)
                    mma16816(acc[mi][ni], afr[cur][mi],
                             bfr[cur][ni >> 1][ni & 1], bfr[cur][ni >> 1][(ni & 1) + 2]);
        }
        stg = (stg + 1) % 3;
    }

    // epilogue: mean bias per col, acc*16 (undo B scaling), store
    float bias2[8][2];
    #pragma unroll
    for (int ni = 0; ni < 8; ++ni) {
        const int n = wn * 64 + ni * 8 + (lane & 3) * 2;
        float s0 = 0.f, s1 = 0.f;
        #pragma unroll
        for (int s = 0; s < 9; ++s) {
            s0 += bias[s * 256 + n];
            s1 += bias[s * 256 + n + 1];
        }
        bias2[ni][0] = s0 * (1.0f / 9.0f);
        bias2[ni][1] = s1 * (1.0f / 9.0f);
    }
    #pragma unroll
    for (int mi = 0; mi < 2; ++mi) {
        const int rbase = wm * 32 + mi * 16 + (lane >> 2);
        #pragma unroll
        for (int ni = 0; ni < 8; ++ni) {
            const int n = wn * 64 + ni * 8 + (lane & 3) * 2;
            #pragma unroll
            for (int hrow = 0; hrow < 2; ++hrow) {
                const int row = rbase + hrow * 8;
                const int yy = row >> 5, xx = row & 31;
                float* op = out + (((size_t)b * N_ + n) * 32 + y0 + yy) * 32 + xx;
                op[0]   = acc[mi][ni][2 * hrow]     * 16.0f + bias2[ni][0];
                op[HW_] = acc[mi][ni][2 * hrow + 1] * 16.0f + bias2[ni][1];
            }
        }
    }
}

// ---------------------------------------------------------------------------
extern "C" void kernel_launch(void* const* d_in, const int* in_sizes, int n_in,
                              void* d_out, int out_size) {
    const float* x    = (const float*)d_in[0];
    const float* tw1  = (const float*)d_in[1];
    const float* tw2  = (const float*)d_in[2];
    const float* bias = (const float*)d_in[3];
    float* out = (float*)d_out;

    cudaFuncSetAttribute(gemm_kernel,
                         cudaFuncAttributeMaxDynamicSharedMemorySize, SMEM_TOT);

    prep_kernel<<<PREP_BLKS, 256>>>(tw1, tw2, x);
    gemm_kernel<<<128, 512, SMEM_TOT>>>(bias, out);
}